// round 1
// baseline (speedup 1.0000x reference)
#include <cuda_runtime.h>
#include <math.h>

#define BB 16
#define MM 60
#define TT 80
#define NA 128
#define NL 64
#define NP 20
#define NLP (NL*NP)

// Scratch for per-(b,m) partial scores between kernels (no allocations allowed).
__device__ float g_partial[BB*MM];

__global__ __launch_bounds__(320) void score_kernel(
    const float* __restrict__ all_trajs,
    const float* __restrict__ agents_now,
    const float* __restrict__ agents_mask,
    const float* __restrict__ map_lanes,
    const float* __restrict__ lanes_mask)
{
    __shared__ float2 s_ag[NA];
    __shared__ float2 s_ln[NLP];
    __shared__ float  s_jerk[TT];   // only first TT-3 used
    __shared__ int    s_coll, s_undr;

    const int bm  = blockIdx.x;
    const int b   = bm / MM;
    const int tid = threadIdx.x;          // 0..319

    if (tid == 0) { s_coll = 0; s_undr = 0; }

    // Stage agents (x,y) into shared; invalid -> far away (sqdist ~1e36, fails
    // <4 test and triggers >9 test exactly like the +BIG penalty in the ref).
    for (int i = tid; i < NA; i += blockDim.x) {
        float valid = agents_mask[b*NA + i];
        float ax = agents_now[(b*NA + i)*4 + 0];
        float ay = agents_now[(b*NA + i)*4 + 1];
        if (valid == 0.0f) { ax = 1e18f; ay = 0.0f; }
        s_ag[i] = make_float2(ax, ay);
    }
    // Stage lane points; lane mask repeats per point (jnp.repeat(mask, P)).
    for (int j = tid; j < NLP; j += blockDim.x) {
        int l = j / NP;
        float valid = lanes_mask[b*NL + l];
        float x = map_lanes[(size_t)((b*NL)*NP + j)*3 + 0];
        float y = map_lanes[(size_t)((b*NL)*NP + j)*3 + 1];
        if (valid == 0.0f) { x = 1e18f; y = 0.0f; }
        s_ln[j] = make_float2(x, y);
    }

    const float* traj = all_trajs + (size_t)bm * TT * 3;

    // Comfort: jerk[t] = x[t+3] - 3x[t+2] + 3x[t+1] - x[t], t in [0, T-3)
    if (tid < TT-3) {
        int t = tid;
        float jx = traj[(t+3)*3+0] - 3.0f*traj[(t+2)*3+0] + 3.0f*traj[(t+1)*3+0] - traj[t*3+0];
        float jy = traj[(t+3)*3+1] - 3.0f*traj[(t+2)*3+1] + 3.0f*traj[(t+1)*3+1] - traj[t*3+1];
        s_jerk[tid] = sqrtf(jx*jx + jy*jy);
    }
    __syncthreads();

    // 4 threads per timestep, each covers 1/4 of the points.
    const int t = tid >> 2;          // 0..79
    const int q = tid & 3;
    const float ex = traj[t*3+0];
    const float ey = traj[t*3+1];

    float mina = 3.4e38f, minl = 3.4e38f;
    #pragma unroll 8
    for (int i = q; i < NA; i += 4) {
        float dx = ex - s_ag[i].x;
        float dy = ey - s_ag[i].y;
        mina = fminf(mina, dx*dx + dy*dy);
    }
    #pragma unroll 8
    for (int j = q; j < NLP; j += 4) {
        float dx = ex - s_ln[j].x;
        float dy = ey - s_ln[j].y;
        minl = fminf(minl, dx*dx + dy*dy);
    }
    // Combine the 4 partials (q lanes are adjacent within the warp).
    mina = fminf(mina, __shfl_xor_sync(0xffffffffu, mina, 1));
    mina = fminf(mina, __shfl_xor_sync(0xffffffffu, mina, 2));
    minl = fminf(minl, __shfl_xor_sync(0xffffffffu, minl, 1));
    minl = fminf(minl, __shfl_xor_sync(0xffffffffu, minl, 2));

    if (q == 0) {
        if (mina < 4.0f) atomicAdd(&s_coll, 1);   // min_dist < 2.0
        if (minl > 9.0f) atomicAdd(&s_undr, 1);   // min_lane_dist > 3.0
    }
    __syncthreads();

    if (tid == 0) {
        float js = 0.0f;
        for (int i = 0; i < TT-3; i++) js += s_jerk[i];   // fixed order -> deterministic
        float comfort   = -js / (float)(TT-3);
        float progress  = traj[(TT-1)*3 + 0];
        float collision = -(float)s_coll / (float)TT;
        float drivable  = -(float)s_undr / (float)TT;
        g_partial[bm] = 0.1f*comfort + 0.5f*progress + 1.0f*collision + 0.3f*drivable;
    }
}

__global__ __launch_bounds__(64) void select_kernel(
    const float* __restrict__ mode_logits,
    const float* __restrict__ all_trajs,
    float* __restrict__ out,
    int write_idx)
{
    __shared__ float red[64];
    __shared__ float s_score[MM];
    __shared__ int   s_sel;

    const int b   = blockIdx.x;
    const int tid = threadIdx.x;     // 0..63

    float l = (tid < MM) ? mode_logits[b*MM + tid] : -3.4e38f;

    // max over logits
    red[tid] = l; __syncthreads();
    for (int s = 32; s > 0; s >>= 1) {
        if (tid < s) red[tid] = fmaxf(red[tid], red[tid+s]);
        __syncthreads();
    }
    float mx = red[0]; __syncthreads();

    float e = (tid < MM) ? __expf(l - mx) : 0.0f;
    red[tid] = e; __syncthreads();
    for (int s = 32; s > 0; s >>= 1) {
        if (tid < s) red[tid] += red[tid+s];
        __syncthreads();
    }
    float sum = red[0];

    if (tid < MM) s_score[tid] = e / sum + g_partial[b*MM + tid];
    __syncthreads();

    if (tid == 0) {
        // First-max argmax (matches jnp.argmax tie-breaking).
        float best = s_score[0]; int bi = 0;
        for (int i = 1; i < MM; i++) {
            if (s_score[i] > best) { best = s_score[i]; bi = i; }
        }
        s_sel = bi;
    }
    __syncthreads();

    const int sel = s_sel;
    const float* src = all_trajs + (size_t)(b*MM + sel) * TT * 3;
    for (int i = tid; i < TT*3; i += blockDim.x)
        out[(size_t)b*TT*3 + i] = src[i];
    if (tid == 0 && write_idx) out[BB*TT*3 + b] = (float)sel;
}

extern "C" void kernel_launch(void* const* d_in, const int* in_sizes, int n_in,
                              void* d_out, int out_size)
{
    const float* mode_logits    = (const float*)d_in[0];
    const float* all_trajs      = (const float*)d_in[1];
    const float* agents_now     = (const float*)d_in[2];
    const float* agents_mask    = (const float*)d_in[3];
    const float* map_lanes      = (const float*)d_in[4];
    const float* map_lanes_mask = (const float*)d_in[5];
    float* out = (float*)d_out;

    int write_idx = (out_size >= BB*TT*3 + BB) ? 1 : 0;

    score_kernel<<<BB*MM, 320>>>(all_trajs, agents_now, agents_mask,
                                 map_lanes, map_lanes_mask);
    select_kernel<<<BB, 64>>>(mode_logits, all_trajs, out, write_idx);
}